// round 3
// baseline (speedup 1.0000x reference)
#include <cuda_runtime.h>
#include <math.h>

// Shapes
#define BB 512
#define TT 512
#define DD 128
#define HH 64

// Scratch (device globals). Padded +4 time-slabs so the scan prefetch needs no bounds check.
__device__ float g_pre[(size_t)(TT + 4) * BB * HH];
__device__ float g_ball[(size_t)(TT + 4) * BB * 8];

typedef unsigned long long ull;

// ---------------- packed fp32x2 helpers (Blackwell FFMA2) ----------------
__device__ __forceinline__ ull fma2(ull a, ull b, ull c) {
    ull d;
    asm("fma.rn.f32x2 %0, %1, %2, %3;" : "=l"(d) : "l"(a), "l"(b), "l"(c));
    return d;
}
__device__ __forceinline__ ull mul2(ull a, ull b) {
    ull d;
    asm("mul.rn.f32x2 %0, %1, %2;" : "=l"(d) : "l"(a), "l"(b));
    return d;
}
__device__ __forceinline__ ull add2(ull a, ull b) {
    ull d;
    asm("add.rn.f32x2 %0, %1, %2;" : "=l"(d) : "l"(a), "l"(b));
    return d;
}
__device__ __forceinline__ ull pack2(float lo, float hi) {
    ull d;
    asm("mov.b64 %0, {%1, %2};" : "=l"(d) : "f"(lo), "f"(hi));
    return d;
}
__device__ __forceinline__ void unpack2(ull v, float& lo, float& hi) {
    asm("mov.b64 {%0, %1}, %2;" : "=f"(lo), "=f"(hi) : "l"(v));
}

// ---------------- fast transcendentals (HW MUFU tanh) ----------------
__device__ __forceinline__ float tanh_fast(float x) {
    float y;
    asm("tanh.approx.f32 %0, %1;" : "=f"(y) : "f"(x));
    return y;
}
__device__ __forceinline__ float gelu_fast(float x) {
    float x2 = x * x;
    float u = x * fmaf(x2, 0.0356774081f, 0.7978845608f);
    float t = tanh_fast(u);
    return x * fmaf(t, 0.5f, 0.5f);
}

// =====================================================================
// Phase 1 (v3): block = (fixed t, 128 consecutive b). One token/thread.
// Coalesced x loads via smem x-stage; outputs transposed through smem
// and flushed as coalesced block stores.
// =====================================================================
// dynamic smem layout (floats):
#define OFF_W1 0          // 8192
#define OFF_WC1H 8192     // 4096
#define OFF_WINN 12288    // 320
#define OFF_STAGE 12608   // 8704 (x-stage uses first 128*33=4224; po-stage 128*68=8704)
#define OFF_STAGEB 21312  // 1536 (128*12)
#define SMEM_FLOATS 22848
#define SMEM_BYTES (SMEM_FLOATS * 4)

__global__ __launch_bounds__(128) void phase1_kernel(
    const float* __restrict__ x, const float* __restrict__ W1,
    const float* __restrict__ b1, const float* __restrict__ ln_g,
    const float* __restrict__ ln_b, const float* __restrict__ W_inn,
    const float* __restrict__ b_inn, const float* __restrict__ Wc1,
    const float* __restrict__ bc1) {
    extern __shared__ float sm[];
    float* sW1 = sm + OFF_W1;
    float* sWc1h = sm + OFF_WC1H;
    float* sWinn = sm + OFF_WINN;
    float* stage = sm + OFF_STAGE;
    float* stageB = sm + OFF_STAGEB;

    const int tid = threadIdx.x;
    const int t = blockIdx.x >> 2;
    const int b0 = (blockIdx.x & 3) << 7;

    for (int i = tid; i < DD * HH; i += 128) sW1[i] = W1[i];
    for (int i = tid; i < HH * HH; i += 128) sWc1h[i] = Wc1[5 * HH + i];
    for (int i = tid; i < HH * 5; i += 128) sWinn[i] = W_inn[i];

    // ---- GEMM1 (K-chunked through x-stage) ----
    ull acc[32];
    const ull* b1p = reinterpret_cast<const ull*>(b1);
#pragma unroll
    for (int q = 0; q < 32; q++) acc[q] = __ldg(b1p + q);

#pragma unroll 1
    for (int c = 0; c < 4; c++) {
        __syncthreads();
        // cooperative coalesced load of x[:, c*32 : c*32+32] for rows b0..b0+127
#pragma unroll
        for (int j = 0; j < 8; j++) {
            int i = tid + j * 128;
            int r = i >> 3, f = i & 7;
            float4 v = __ldg(reinterpret_cast<const float4*>(
                                 x + ((size_t)(b0 + r) * TT + t) * DD + c * 32) + f);
            float* d = stage + r * 33 + f * 4;
            d[0] = v.x; d[1] = v.y; d[2] = v.z; d[3] = v.w;
        }
        __syncthreads();
#pragma unroll 2
        for (int k = 0; k < 32; k++) {
            float xv = stage[tid * 33 + k];
            ull xd = pack2(xv, xv);
            const ulonglong2* wr =
                reinterpret_cast<const ulonglong2*>(sW1 + (c * 32 + k) * HH);
#pragma unroll
            for (int q2 = 0; q2 < 16; q2++) {
                ulonglong2 w = wr[q2];
                acc[2 * q2] = fma2(xd, w.x, acc[2 * q2]);
                acc[2 * q2 + 1] = fma2(xd, w.y, acc[2 * q2 + 1]);
            }
        }
    }

    float h[HH];
#pragma unroll
    for (int q = 0; q < 32; q++) unpack2(acc[q], h[2 * q], h[2 * q + 1]);

    // ---- LayerNorm + gelu ----
    float s1 = 0.f, s2 = 0.f;
#pragma unroll
    for (int j = 0; j < HH; j++) { s1 += h[j]; s2 += h[j] * h[j]; }
    const float mean = s1 * (1.0f / HH);
    const float var = s2 * (1.0f / HH) - mean * mean;
    const float rstd = rsqrtf(var + 1e-5f);
#pragma unroll
    for (int j = 0; j < HH; j++) {
        float v = (h[j] - mean) * rstd * __ldg(ln_g + j) + __ldg(ln_b + j);
        h[j] = gelu_fast(v);
    }

    // ---- GEMM2: pre = h @ Wc1_h + bc1 ----
    ull po[32];
    const ull* bc1p = reinterpret_cast<const ull*>(bc1);
#pragma unroll
    for (int q = 0; q < 32; q++) po[q] = __ldg(bc1p + q);
#pragma unroll 2
    for (int k = 0; k < HH; k++) {
        ull hd = pack2(h[k], h[k]);
        const ulonglong2* wr = reinterpret_cast<const ulonglong2*>(sWc1h + k * HH);
#pragma unroll
        for (int q2 = 0; q2 < 16; q2++) {
            ulonglong2 w = wr[q2];
            po[2 * q2] = fma2(hd, w.x, po[2 * q2]);
            po[2 * q2 + 1] = fma2(hd, w.y, po[2 * q2 + 1]);
        }
    }

    // ---- b_all = h @ W_inn + b_inn ----
    float bb[5];
#pragma unroll
    for (int s = 0; s < 5; s++) bb[s] = __ldg(b_inn + s);
#pragma unroll 4
    for (int k = 0; k < HH; k++) {
        float hk = h[k];
#pragma unroll
        for (int s = 0; s < 5; s++) bb[s] = fmaf(hk, sWinn[k * 5 + s], bb[s]);
    }

    // ---- transpose-stage + coalesced flush ----
    __syncthreads();  // x-stage reads done; reuse stage for po
#pragma unroll
    for (int q2 = 0; q2 < 16; q2++) {
        float l0, h0, l1, h1;
        unpack2(po[2 * q2], l0, h0);
        unpack2(po[2 * q2 + 1], l1, h1);
        *reinterpret_cast<float4*>(stage + tid * 68 + q2 * 4) =
            make_float4(l0, h0, l1, h1);
    }
    *reinterpret_cast<float4*>(stageB + tid * 12) =
        make_float4(bb[0], bb[1], bb[2], bb[3]);
    stageB[tid * 12 + 4] = bb[4];
    __syncthreads();

    float4* gp = reinterpret_cast<float4*>(g_pre + ((size_t)t * BB + b0) * HH);
#pragma unroll
    for (int j = 0; j < 16; j++) {
        int i = tid + j * 128;
        int r = i >> 4, cq = i & 15;
        const float* s = stage + r * 68 + cq * 4;
        gp[i] = make_float4(s[0], s[1], s[2], s[3]);
    }
    float4* gb = reinterpret_cast<float4*>(g_ball + ((size_t)t * BB + b0) * 8);
#pragma unroll
    for (int j = 0; j < 2; j++) {
        int i = tid + j * 128;
        int r = i >> 1, cq = i & 1;
        const float* s = stageB + r * 12 + cq * 4;
        gb[i] = make_float4(s[0], s[1], s[2], s[3]);
    }
}

// =====================================================================
// Phase 2 scan (v3): 8 lanes/row, 4 rows/warp, fp32x2-packed inner loop.
// =====================================================================
__device__ __forceinline__ float sigmoidf_(float v) { return 1.0f / (1.0f + expf(-v)); }

__global__ __launch_bounds__(32) void scan_kernel(
    const float* __restrict__ Wc1, const float* __restrict__ Wc2,
    const float* __restrict__ bc2, const float* __restrict__ corr_scale,
    const float* __restrict__ raw_aL, const float* __restrict__ raw_aT,
    const float* __restrict__ raw_g, const float* __restrict__ raw_aR,
    const float* __restrict__ omega, float* __restrict__ out) {
    const int lane = threadIdx.x;
    const int sub = lane & 7;
    const int row = blockIdx.x * 4 + (lane >> 3);
    const int j0 = sub * 8;

    // weight pairs (registers)
    ull w1p[5][4], w2p[5][4], pinit[5];
#pragma unroll
    for (int k = 0; k < 5; k++)
#pragma unroll
        for (int p = 0; p < 4; p++)
            w1p[k][p] = pack2(__ldg(&Wc1[k * 64 + j0 + 2 * p]),
                              __ldg(&Wc1[k * 64 + j0 + 2 * p + 1]));
#pragma unroll
    for (int k = 0; k < 5; k++)
#pragma unroll
        for (int p = 0; p < 4; p++)
            w2p[k][p] = pack2(__ldg(&Wc2[(j0 + 2 * p) * 5 + k]),
                              __ldg(&Wc2[(j0 + 2 * p + 1) * 5 + k]));
#pragma unroll
    for (int k = 0; k < 5; k++)
        pinit[k] = pack2(sub == 0 ? __ldg(bc2 + k) : 0.0f, 0.0f);

    const float aL = sigmoidf_(__ldg(raw_aL)) * 0.15f + 0.85f;
    const float aT = sigmoidf_(__ldg(raw_aT)) * 0.25f + 0.70f;
    const float gg = sigmoidf_(__ldg(raw_g)) * 0.20f + 0.80f;
    const float aR = sigmoidf_(__ldg(raw_aR)) * 0.40f;
    const float om = __ldg(omega);
    const float gc = gg * cosf(om), gs = gg * sinf(om), ngs = -gs;
    const float cs = __ldg(corr_scale);
    const ull C1p = pack2(0.0356774081f, 0.0356774081f);
    const ull C2p = pack2(0.7978845608f, 0.7978845608f);
    const ull HALFp = pack2(0.5f, 0.5f);

    float s0 = 0.f, s1 = 0.f, s2v = 0.f, s3 = 0.f, s4 = 0.f;

    ull pb2[4][4];
    float bb[4][5];

#pragma unroll
    for (int u = 0; u < 4; u++) {
        const ulonglong2* pp = reinterpret_cast<const ulonglong2*>(
            g_pre + ((size_t)u * BB + row) * HH + j0);
        ulonglong2 a0 = __ldg(pp), a1 = __ldg(pp + 1);
        pb2[u][0] = a0.x; pb2[u][1] = a0.y; pb2[u][2] = a1.x; pb2[u][3] = a1.y;
        const float* bp = g_ball + ((size_t)u * BB + row) * 8;
        float4 c = __ldg(reinterpret_cast<const float4*>(bp));
        bb[u][0] = c.x; bb[u][1] = c.y; bb[u][2] = c.z; bb[u][3] = c.w;
        bb[u][4] = __ldg(bp + 4);
    }

    for (int tb = 0; tb < TT; tb += 4) {
#pragma unroll
        for (int u = 0; u < 4; u++) {
            const int t = tb + u;
            float sl0 = fmaf(s0, aL, bb[u][0]);
            float sl1 = fmaf(s1, aT, bb[u][1]);
            float sl2 = fmaf(s2v, gc, fmaf(s3, gs, bb[u][2]));
            float sl3 = fmaf(s3, gc, fmaf(s2v, ngs, bb[u][3]));
            float sl4 = fmaf(s4, aR, bb[u][4]);

            ull sl0p = pack2(sl0, sl0), sl1p = pack2(sl1, sl1),
                sl2p = pack2(sl2, sl2), sl3p = pack2(sl3, sl3),
                sl4p = pack2(sl4, sl4);

            ull accA[5], accB[5];
#pragma unroll
            for (int k = 0; k < 5; k++) { accA[k] = pinit[k]; accB[k] = 0ull; }

#pragma unroll
            for (int p = 0; p < 4; p++) {
                // z (tree, depth 3)
                ull zA = fma2(sl0p, w1p[0][p], pb2[u][p]);
                ull m = mul2(sl1p, w1p[1][p]);
                zA = fma2(sl3p, w1p[3][p], zA);
                m = fma2(sl2p, w1p[2][p], m);
                m = fma2(sl4p, w1p[4][p], m);
                ull z = add2(zA, m);
                // gelu pair
                ull x2 = mul2(z, z);
                ull up = fma2(x2, C1p, C2p);
                ull u2 = mul2(z, up);
                float ulo, uhi;
                unpack2(u2, ulo, uhi);
                ull tp = pack2(tanh_fast(ulo), tanh_fast(uhi));
                ull r = fma2(tp, HALFp, HALFp);
                ull hg = mul2(z, r);
                // accumulate
                if (p & 1) {
#pragma unroll
                    for (int k = 0; k < 5; k++) accB[k] = fma2(hg, w2p[k][p], accB[k]);
                } else {
#pragma unroll
                    for (int k = 0; k < 5; k++) accA[k] = fma2(hg, w2p[k][p], accA[k]);
                }
            }

            float p0, p1, p2, p3, p4;
            {
                float lo, hi;
                ull tot;
                tot = add2(accA[0], accB[0]); unpack2(tot, lo, hi); p0 = lo + hi;
                tot = add2(accA[1], accB[1]); unpack2(tot, lo, hi); p1 = lo + hi;
                tot = add2(accA[2], accB[2]); unpack2(tot, lo, hi); p2 = lo + hi;
                tot = add2(accA[3], accB[3]); unpack2(tot, lo, hi); p3 = lo + hi;
                tot = add2(accA[4], accB[4]); unpack2(tot, lo, hi); p4 = lo + hi;
            }

            // prefetch t+4 (arrays padded; no guard needed)
            {
                const ulonglong2* pp = reinterpret_cast<const ulonglong2*>(
                    g_pre + ((size_t)(t + 4) * BB + row) * HH + j0);
                ulonglong2 a0 = __ldg(pp), a1 = __ldg(pp + 1);
                pb2[u][0] = a0.x; pb2[u][1] = a0.y; pb2[u][2] = a1.x; pb2[u][3] = a1.y;
                const float* bp = g_ball + ((size_t)(t + 4) * BB + row) * 8;
                float4 c = __ldg(reinterpret_cast<const float4*>(bp));
                bb[u][0] = c.x; bb[u][1] = c.y; bb[u][2] = c.z; bb[u][3] = c.w;
                bb[u][4] = __ldg(bp + 4);
            }

            // butterfly reduce across 8 lanes
#pragma unroll
            for (int m = 4; m >= 1; m >>= 1) {
                p0 += __shfl_xor_sync(0xffffffffu, p0, m);
                p1 += __shfl_xor_sync(0xffffffffu, p1, m);
                p2 += __shfl_xor_sync(0xffffffffu, p2, m);
                p3 += __shfl_xor_sync(0xffffffffu, p3, m);
                p4 += __shfl_xor_sync(0xffffffffu, p4, m);
            }

            s0 = fmaf(cs, tanh_fast(p0), sl0);
            s1 = fmaf(cs, tanh_fast(p1), sl1);
            s2v = fmaf(cs, tanh_fast(p2), sl2);
            s3 = fmaf(cs, tanh_fast(p3), sl3);
            s4 = fmaf(cs, tanh_fast(p4), sl4);
        }
    }

    if (sub == 0) {
        out[row * 5 + 0] = s0;
        out[row * 5 + 1] = s1;
        out[row * 5 + 2] = s2v;
        out[row * 5 + 3] = s3;
        out[row * 5 + 4] = s4;
    }
}

// =====================================================================
extern "C" void kernel_launch(void* const* d_in, const int* in_sizes, int n_in,
                              void* d_out, int out_size) {
    const float* x = (const float*)d_in[0];
    const float* W1 = (const float*)d_in[1];
    const float* b1 = (const float*)d_in[2];
    const float* ln_g = (const float*)d_in[3];
    const float* ln_b = (const float*)d_in[4];
    const float* W_inn = (const float*)d_in[5];
    const float* b_inn = (const float*)d_in[6];
    const float* Wc1 = (const float*)d_in[7];
    const float* bc1 = (const float*)d_in[8];
    const float* Wc2 = (const float*)d_in[9];
    const float* bc2 = (const float*)d_in[10];
    const float* corr_scale = (const float*)d_in[11];
    const float* raw_aL = (const float*)d_in[12];
    const float* raw_aT = (const float*)d_in[13];
    const float* raw_g = (const float*)d_in[14];
    const float* raw_aR = (const float*)d_in[15];
    const float* omega = (const float*)d_in[16];
    float* out = (float*)d_out;

    cudaFuncSetAttribute(phase1_kernel, cudaFuncAttributeMaxDynamicSharedMemorySize,
                         SMEM_BYTES);

    phase1_kernel<<<TT * 4, 128, SMEM_BYTES>>>(x, W1, b1, ln_g, ln_b, W_inn, b_inn,
                                               Wc1, bc1);
    scan_kernel<<<BB / 4, 32>>>(Wc1, Wc2, bc2, corr_scale, raw_aL, raw_aT, raw_g,
                                raw_aR, omega, out);
}

// round 6
// speedup vs baseline: 1.2372x; 1.2372x over previous
#include <cuda_runtime.h>
#include <math.h>

// Shapes
#define BB 512
#define TT 512
#define DD 128
#define HH 64

// Scratch (device globals). Padded +8 time-slabs: scan prefetch depth 8, no bounds check.
__device__ float g_pre[(size_t)(TT + 8) * BB * HH];
__device__ float g_ball[(size_t)(TT + 8) * BB * 8];

typedef unsigned long long ull;

// ---------------- packed fp32x2 helpers (Blackwell FFMA2) ----------------
__device__ __forceinline__ ull fma2(ull a, ull b, ull c) {
    ull d;
    asm("fma.rn.f32x2 %0, %1, %2, %3;" : "=l"(d) : "l"(a), "l"(b), "l"(c));
    return d;
}
__device__ __forceinline__ ull pack2(float lo, float hi) {
    ull d;
    asm("mov.b64 %0, {%1, %2};" : "=l"(d) : "f"(lo), "f"(hi));
    return d;
}
__device__ __forceinline__ void unpack2(ull v, float& lo, float& hi) {
    asm("mov.b64 {%0, %1}, %2;" : "=f"(lo), "=f"(hi) : "l"(v));
}

// ---------------- fast transcendentals ----------------
__device__ __forceinline__ float tanh_fast(float x) {
    float y;
    asm("tanh.approx.f32 %0, %1;" : "=f"(y) : "f"(x));
    return y;
}
__device__ __forceinline__ float gelu_fast(float x) {
    float x2 = x * x;
    float u = x * fmaf(x2, 0.0356774081f, 0.7978845608f);
    float t = tanh_fast(u);
    return x * fmaf(t, 0.5f, 0.5f);
}
// Warp-wide s32 add reduction (HW REDUX, sm_80+; result broadcast to all lanes)
__device__ __forceinline__ int redux_add_s32(int v) {
    int r;
    asm("redux.sync.add.s32 %0, %1, 0xffffffff;" : "=r"(r) : "r"(v));
    return r;
}
__device__ __forceinline__ float sigmoidf_(float v) { return 1.0f / (1.0f + expf(-v)); }

// =====================================================================
// Phase 1 (v4.1): register-tiled. Block = (fixed t, 128 consecutive b),
// 256 threads; thread computes 4 tokens x 8 cols.
//   colg = tid & 7 (owns cols colg*8..+7), tokg = tid >> 3 (tokens tokg*4..+3)
// =====================================================================
// dynamic smem layout (float offsets):
//  sWc1h @ 0      (4096)
//  sWinn @ 4096   (320)
//  sBall @ 4416   (1536)   128 tokens x 12
//  region @ 5952  (12416):
//    GEMM1 phase:  sW1 @ 5952 (8192), sX @ 14144 (32 x 132 = 4224)
//    GEMM2 phase:  shT @ 5952 (64 x 132 = 8448)
//    flush phase:  stage @ 5952 (128 x 68 = 8704)
#define P1_SMEM_FLOATS 18368
#define P1_SMEM_BYTES (P1_SMEM_FLOATS * 4)

__global__ __launch_bounds__(256) void phase1_kernel(
    const float* __restrict__ x, const float* __restrict__ W1,
    const float* __restrict__ b1, const float* __restrict__ ln_g,
    const float* __restrict__ ln_b, const float* __restrict__ W_inn,
    const float* __restrict__ b_inn, const float* __restrict__ Wc1,
    const float* __restrict__ bc1) {
    extern __shared__ float sm[];
    float* sWc1h = sm;            // 4096
    float* sWinn = sm + 4096;     // 320
    float* sBall = sm + 4416;     // 1536
    float* region = sm + 5952;
    float* sW1 = region;          // 8192
    float* sX = region + 8192;    // 4224
    float* shT = region;          // 8448 (overlay)
    float* stage = region;        // 8704 (overlay)

    const int tid = threadIdx.x;
    const int t = blockIdx.x >> 2;
    const int b0 = (blockIdx.x & 3) << 7;
    const int colg = tid & 7;
    const int tokg = tid >> 3;

    // cooperative weight loads (strided loops — do NOT truncate!)
    for (int i = tid; i < HH * HH; i += 256) sWc1h[i] = Wc1[5 * HH + i];
    for (int i = tid; i < DD * HH; i += 256) sW1[i] = W1[i];
    for (int i = tid; i < HH * 5; i += 256) sWinn[i] = W_inn[i];

    // per-thread constants
    ull b1q[4], bc1q[4];
    const ull* b1p = reinterpret_cast<const ull*>(b1);
    const ull* bc1p = reinterpret_cast<const ull*>(bc1);
#pragma unroll
    for (int q = 0; q < 4; q++) {
        b1q[q] = __ldg(b1p + colg * 4 + q);
        bc1q[q] = __ldg(bc1p + colg * 4 + q);
    }
    float lng[8], lnb[8];
#pragma unroll
    for (int j = 0; j < 8; j++) {
        lng[j] = __ldg(ln_g + colg * 8 + j);
        lnb[j] = __ldg(ln_b + colg * 8 + j);
    }

    // ---- GEMM1: acc[tt][q] over 4 tokens x 8 cols (4 f32x2 pairs) ----
    ull acc[4][4];
#pragma unroll
    for (int tt = 0; tt < 4; tt++)
#pragma unroll
        for (int q = 0; q < 4; q++) acc[tt][q] = b1q[q];

#pragma unroll 1
    for (int c = 0; c < 4; c++) {
        __syncthreads();  // previous chunk's sX reads done (also covers weight loads)
#pragma unroll
        for (int j = 0; j < 4; j++) {
            int i = tid + j * 256;  // 0..1023
            int tok = i >> 3, kq = i & 7;
            float4 v = __ldg(reinterpret_cast<const float4*>(
                                 x + ((size_t)(b0 + tok) * TT + t) * DD + c * 32) +
                             kq);
            sX[(kq * 4 + 0) * 132 + tok] = v.x;
            sX[(kq * 4 + 1) * 132 + tok] = v.y;
            sX[(kq * 4 + 2) * 132 + tok] = v.z;
            sX[(kq * 4 + 3) * 132 + tok] = v.w;
        }
        __syncthreads();
#pragma unroll 4
        for (int kk = 0; kk < 32; kk++) {
            float4 xv = *reinterpret_cast<const float4*>(&sX[kk * 132 + tokg * 4]);
            const ulonglong2* wr = reinterpret_cast<const ulonglong2*>(
                sW1 + (c * 32 + kk) * HH + colg * 8);
            ulonglong2 l0 = wr[0], l1 = wr[1];
            float xs[4] = {xv.x, xv.y, xv.z, xv.w};
#pragma unroll
            for (int tt = 0; tt < 4; tt++) {
                ull xd = pack2(xs[tt], xs[tt]);
                acc[tt][0] = fma2(xd, l0.x, acc[tt][0]);
                acc[tt][1] = fma2(xd, l0.y, acc[tt][1]);
                acc[tt][2] = fma2(xd, l1.x, acc[tt][2]);
                acc[tt][3] = fma2(xd, l1.y, acc[tt][3]);
            }
        }
    }

    // ---- LN (reduce across 8 col-owner lanes) + gelu ----
    float hv[4][8];
#pragma unroll
    for (int tt = 0; tt < 4; tt++)
#pragma unroll
        for (int q = 0; q < 4; q++) unpack2(acc[tt][q], hv[tt][2 * q], hv[tt][2 * q + 1]);

#pragma unroll
    for (int tt = 0; tt < 4; tt++) {
        float s1 = 0.f, s2 = 0.f;
#pragma unroll
        for (int j = 0; j < 8; j++) { s1 += hv[tt][j]; s2 += hv[tt][j] * hv[tt][j]; }
#pragma unroll
        for (int m = 1; m <= 4; m <<= 1) {
            s1 += __shfl_xor_sync(0xffffffffu, s1, m);
            s2 += __shfl_xor_sync(0xffffffffu, s2, m);
        }
        float mean = s1 * (1.0f / HH);
        float var = s2 * (1.0f / HH) - mean * mean;
        float rstd = rsqrtf(var + 1e-5f);
#pragma unroll
        for (int j = 0; j < 8; j++) {
            float v = (hv[tt][j] - mean) * rstd * lng[j] + lnb[j];
            hv[tt][j] = gelu_fast(v);
        }
    }

    __syncthreads();  // all GEMM1 smem reads done; overwrite region with shT
#pragma unroll
    for (int tt = 0; tt < 4; tt++)
#pragma unroll
        for (int j = 0; j < 8; j++)
            shT[(colg * 8 + j) * 132 + tokg * 4 + tt] = hv[tt][j];
    __syncthreads();

    // ---- GEMM2: po = h @ Wc1_h + bc1 ----
    ull po[4][4];
#pragma unroll
    for (int tt = 0; tt < 4; tt++)
#pragma unroll
        for (int q = 0; q < 4; q++) po[tt][q] = bc1q[q];
#pragma unroll 4
    for (int k = 0; k < HH; k++) {
        float4 hv4 = *reinterpret_cast<const float4*>(&shT[k * 132 + tokg * 4]);
        const ulonglong2* wr =
            reinterpret_cast<const ulonglong2*>(sWc1h + k * HH + colg * 8);
        ulonglong2 l0 = wr[0], l1 = wr[1];
        float hs[4] = {hv4.x, hv4.y, hv4.z, hv4.w};
#pragma unroll
        for (int tt = 0; tt < 4; tt++) {
            ull hd = pack2(hs[tt], hs[tt]);
            po[tt][0] = fma2(hd, l0.x, po[tt][0]);
            po[tt][1] = fma2(hd, l0.y, po[tt][1]);
            po[tt][2] = fma2(hd, l1.x, po[tt][2]);
            po[tt][3] = fma2(hd, l1.y, po[tt][3]);
        }
    }

    // ---- b_all = h @ W_inn + b_inn (one token per thread, tid<128) ----
    if (tid < 128) {
        float bbv[5];
#pragma unroll
        for (int s = 0; s < 5; s++) bbv[s] = __ldg(b_inn + s);
#pragma unroll 4
        for (int k = 0; k < HH; k++) {
            float hk = shT[k * 132 + tid];
#pragma unroll
            for (int s = 0; s < 5; s++) bbv[s] = fmaf(hk, sWinn[k * 5 + s], bbv[s]);
        }
        *reinterpret_cast<float4*>(sBall + tid * 12) =
            make_float4(bbv[0], bbv[1], bbv[2], bbv[3]);
        sBall[tid * 12 + 4] = bbv[4];
        sBall[tid * 12 + 5] = 0.f;
        sBall[tid * 12 + 6] = 0.f;
        sBall[tid * 12 + 7] = 0.f;
    }

    __syncthreads();  // shT reads done; overwrite region with stage
#pragma unroll
    for (int tt = 0; tt < 4; tt++) {
        float f0, f1, f2, f3, f4, f5, f6, f7;
        unpack2(po[tt][0], f0, f1);
        unpack2(po[tt][1], f2, f3);
        unpack2(po[tt][2], f4, f5);
        unpack2(po[tt][3], f6, f7);
        float* d = stage + (tokg * 4 + tt) * 68 + colg * 8;
        *reinterpret_cast<float4*>(d) = make_float4(f0, f1, f2, f3);
        *reinterpret_cast<float4*>(d + 4) = make_float4(f4, f5, f6, f7);
    }
    __syncthreads();

    // ---- coalesced flush ----
    float4* gp = reinterpret_cast<float4*>(g_pre + ((size_t)t * BB + b0) * HH);
#pragma unroll
    for (int j = 0; j < 8; j++) {
        int i = tid + j * 256;  // 0..2047
        int r = i >> 4, cq = i & 15;
        const float* s = stage + r * 68 + cq * 4;
        gp[i] = make_float4(s[0], s[1], s[2], s[3]);
    }
    float4* gb = reinterpret_cast<float4*>(g_ball + ((size_t)t * BB + b0) * 8);
    {
        int i = tid;  // 0..255, exactly 128*8/4 float4s
        int r = i >> 1, cq = i & 1;
        const float* s = sBall + r * 12 + cq * 4;
        gb[i] = make_float4(s[0], s[1], s[2], s[3]);
    }
}

// =====================================================================
// Phase 2 scan (v5): ONE row per warp, 32 lanes, 2 js/lane,
// fixed-point redux.sync.add.s32 reduction. 512 single-warp CTAs.
// Depth-8 register prefetch.
// =====================================================================
#define FXS 1048576.0f            // 2^20
#define FXSI 9.5367431640625e-7f  // 2^-20

__global__ __launch_bounds__(32) void scan_kernel(
    const float* __restrict__ Wc1, const float* __restrict__ Wc2,
    const float* __restrict__ bc2, const float* __restrict__ corr_scale,
    const float* __restrict__ raw_aL, const float* __restrict__ raw_aT,
    const float* __restrict__ raw_g, const float* __restrict__ raw_aR,
    const float* __restrict__ omega, float* __restrict__ out) {
    const int lane = threadIdx.x;
    const int row = blockIdx.x;
    const int j0 = lane * 2;

    float w1s[5][2], w2v[2][5], bc[5];
#pragma unroll
    for (int k = 0; k < 5; k++) {
        w1s[k][0] = __ldg(&Wc1[k * 64 + j0]);
        w1s[k][1] = __ldg(&Wc1[k * 64 + j0 + 1]);
    }
#pragma unroll
    for (int jj = 0; jj < 2; jj++)
#pragma unroll
        for (int k = 0; k < 5; k++) {
            // pre-scale Wc2 by 2^20 so the lane partial is already fixed-point scaled
            w2v[jj][k] = __ldg(&Wc2[(j0 + jj) * 5 + k]) * FXS;
        }
#pragma unroll
    for (int k = 0; k < 5; k++) bc[k] = __ldg(bc2 + k);

    const float aL = sigmoidf_(__ldg(raw_aL)) * 0.15f + 0.85f;
    const float aT = sigmoidf_(__ldg(raw_aT)) * 0.25f + 0.70f;
    const float gg = sigmoidf_(__ldg(raw_g)) * 0.20f + 0.80f;
    const float aR = sigmoidf_(__ldg(raw_aR)) * 0.40f;
    const float om = __ldg(omega);
    const float gc = gg * cosf(om), gs = gg * sinf(om), ngs = -gs;
    const float cs = __ldg(corr_scale);

    float s0 = 0.f, s1 = 0.f, s2v = 0.f, s3 = 0.f, s4 = 0.f;

    float2 pb[8];
    float bbv[8][5];

#pragma unroll
    for (int u = 0; u < 8; u++) {
        pb[u] = __ldg(reinterpret_cast<const float2*>(
            g_pre + ((size_t)u * BB + row) * HH + j0));
        const float* bp = g_ball + ((size_t)u * BB + row) * 8;
        float4 c = __ldg(reinterpret_cast<const float4*>(bp));
        bbv[u][0] = c.x; bbv[u][1] = c.y; bbv[u][2] = c.z; bbv[u][3] = c.w;
        bbv[u][4] = __ldg(bp + 4);
    }

#pragma unroll 1
    for (int tb = 0; tb < TT; tb += 8) {
#pragma unroll
        for (int u = 0; u < 8; u++) {
            const int t = tb + u;
            float sl0 = fmaf(s0, aL, bbv[u][0]);
            float sl1 = fmaf(s1, aT, bbv[u][1]);
            float sl2 = fmaf(s2v, gc, fmaf(s3, gs, bbv[u][2]));
            float sl3 = fmaf(s3, gc, fmaf(s2v, ngs, bbv[u][3]));
            float sl4 = fmaf(s4, aR, bbv[u][4]);

            // z for this lane's 2 columns (shallow trees)
            float za0 = fmaf(sl0, w1s[0][0], pb[u].x);
            float za1 = fmaf(sl0, w1s[0][1], pb[u].y);
            float zb0 = sl1 * w1s[1][0];
            float zb1 = sl1 * w1s[1][1];
            za0 = fmaf(sl2, w1s[2][0], za0);
            za1 = fmaf(sl2, w1s[2][1], za1);
            zb0 = fmaf(sl3, w1s[3][0], zb0);
            zb1 = fmaf(sl3, w1s[3][1], zb1);
            za0 = fmaf(sl4, w1s[4][0], za0);
            za1 = fmaf(sl4, w1s[4][1], za1);
            float z0 = za0 + zb0;
            float z1 = za1 + zb1;

            float hg0 = gelu_fast(z0);
            float hg1 = gelu_fast(z1);

            // lane partials, already scaled by 2^20 (via w2v)
            float p0 = fmaf(hg0, w2v[0][0], hg1 * w2v[1][0]);
            float p1 = fmaf(hg0, w2v[0][1], hg1 * w2v[1][1]);
            float p2 = fmaf(hg0, w2v[0][2], hg1 * w2v[1][2]);
            float p3 = fmaf(hg0, w2v[0][3], hg1 * w2v[1][3]);
            float p4 = fmaf(hg0, w2v[0][4], hg1 * w2v[1][4]);

            // prefetch t+8 (arrays padded, no guard)
            pb[u] = __ldg(reinterpret_cast<const float2*>(
                g_pre + ((size_t)(t + 8) * BB + row) * HH + j0));
            const float* bp = g_ball + ((size_t)(t + 8) * BB + row) * 8;
            float4 c = __ldg(reinterpret_cast<const float4*>(bp));
            bbv[u][0] = c.x; bbv[u][1] = c.y; bbv[u][2] = c.z; bbv[u][3] = c.w;
            bbv[u][4] = __ldg(bp + 4);

            // fixed-point HW warp reduction (broadcasts to all lanes)
            int i0 = redux_add_s32(__float2int_rn(p0));
            int i1 = redux_add_s32(__float2int_rn(p1));
            int i2 = redux_add_s32(__float2int_rn(p2));
            int i3 = redux_add_s32(__float2int_rn(p3));
            int i4 = redux_add_s32(__float2int_rn(p4));

            s0 = fmaf(cs, tanh_fast(fmaf(__int2float_rn(i0), FXSI, bc[0])), sl0);
            s1 = fmaf(cs, tanh_fast(fmaf(__int2float_rn(i1), FXSI, bc[1])), sl1);
            s2v = fmaf(cs, tanh_fast(fmaf(__int2float_rn(i2), FXSI, bc[2])), sl2);
            s3 = fmaf(cs, tanh_fast(fmaf(__int2float_rn(i3), FXSI, bc[3])), sl3);
            s4 = fmaf(cs, tanh_fast(fmaf(__int2float_rn(i4), FXSI, bc[4])), sl4);
        }
    }

    if (lane == 0) {
        out[row * 5 + 0] = s0;
        out[row * 5 + 1] = s1;
        out[row * 5 + 2] = s2v;
        out[row * 5 + 3] = s3;
        out[row * 5 + 4] = s4;
    }
}

// =====================================================================
extern "C" void kernel_launch(void* const* d_in, const int* in_sizes, int n_in,
                              void* d_out, int out_size) {
    const float* x = (const float*)d_in[0];
    const float* W1 = (const float*)d_in[1];
    const float* b1 = (const float*)d_in[2];
    const float* ln_g = (const float*)d_in[3];
    const float* ln_b = (const float*)d_in[4];
    const float* W_inn = (const float*)d_in[5];
    const float* b_inn = (const float*)d_in[6];
    const float* Wc1 = (const float*)d_in[7];
    const float* bc1 = (const float*)d_in[8];
    const float* Wc2 = (const float*)d_in[9];
    const float* bc2 = (const float*)d_in[10];
    const float* corr_scale = (const float*)d_in[11];
    const float* raw_aL = (const float*)d_in[12];
    const float* raw_aT = (const float*)d_in[13];
    const float* raw_g = (const float*)d_in[14];
    const float* raw_aR = (const float*)d_in[15];
    const float* omega = (const float*)d_in[16];
    float* out = (float*)d_out;

    cudaFuncSetAttribute(phase1_kernel, cudaFuncAttributeMaxDynamicSharedMemorySize,
                         P1_SMEM_BYTES);

    phase1_kernel<<<TT * 4, 256, P1_SMEM_BYTES>>>(x, W1, b1, ln_g, ln_b, W_inn,
                                                  b_inn, Wc1, bc1);
    scan_kernel<<<BB, 32>>>(Wc1, Wc2, bc2, corr_scale, raw_aL, raw_aT, raw_g,
                            raw_aR, omega, out);
}

// round 7
// speedup vs baseline: 1.2651x; 1.0225x over previous
#include <cuda_runtime.h>
#include <math.h>

// Shapes
#define BB 512
#define TT 512
#define DD 128
#define HH 64

// Scratch (device globals). Padded +8 time-slabs: scan prefetch depth 8, no bounds check.
__device__ float g_pre[(size_t)(TT + 8) * BB * HH];
__device__ float g_ball[(size_t)(TT + 8) * BB * 8];

typedef unsigned long long ull;

// ---------------- packed fp32x2 helpers (Blackwell FFMA2) ----------------
__device__ __forceinline__ ull fma2(ull a, ull b, ull c) {
    ull d;
    asm("fma.rn.f32x2 %0, %1, %2, %3;" : "=l"(d) : "l"(a), "l"(b), "l"(c));
    return d;
}
__device__ __forceinline__ ull pack2(float lo, float hi) {
    ull d;
    asm("mov.b64 %0, {%1, %2};" : "=l"(d) : "f"(lo), "f"(hi));
    return d;
}
__device__ __forceinline__ void unpack2(ull v, float& lo, float& hi) {
    asm("mov.b64 {%0, %1}, %2;" : "=f"(lo), "=f"(hi) : "l"(v));
}

// ---------------- fast transcendentals ----------------
__device__ __forceinline__ float tanh_fast(float x) {
    float y;
    asm("tanh.approx.f32 %0, %1;" : "=f"(y) : "f"(x));
    return y;
}
__device__ __forceinline__ float gelu_fast(float x) {
    float x2 = x * x;
    float u = x * fmaf(x2, 0.0356774081f, 0.7978845608f);
    float t = tanh_fast(u);
    return x * fmaf(t, 0.5f, 0.5f);
}
// Warp-wide s32 add reduction (HW REDUX, sm_80+; result broadcast to all lanes)
__device__ __forceinline__ int redux_add_s32(int v) {
    int r;
    asm("redux.sync.add.s32 %0, %1, 0xffffffff;" : "=r"(r) : "r"(v));
    return r;
}
__device__ __forceinline__ float sigmoidf_(float v) { return 1.0f / (1.0f + expf(-v)); }

// =====================================================================
// Padding zero kernels (also shift ncu capture index so phase1 lands on
// capture slot 5: launch order is [zpad_pre, phase1, zpad_ball, scan]).
// =====================================================================
__global__ __launch_bounds__(256) void zpad_pre_kernel() {
    size_t i = (size_t)blockIdx.x * 256 + threadIdx.x;  // 65536 float4
    reinterpret_cast<float4*>(g_pre + (size_t)TT * BB * HH)[i] =
        make_float4(0.f, 0.f, 0.f, 0.f);
}
__global__ __launch_bounds__(256) void zpad_ball_kernel() {
    size_t i = (size_t)blockIdx.x * 256 + threadIdx.x;  // 8192 float4
    reinterpret_cast<float4*>(g_ball + (size_t)TT * BB * 8)[i] =
        make_float4(0.f, 0.f, 0.f, 0.f);
}

// =====================================================================
// Phase 1 (v5): register-tiled, double-buffered x prefetch.
// Block = (fixed t, 128 consecutive b), 256 threads; thread computes
// 4 tokens x 8 cols. colg = tid & 7, tokg = tid >> 3.
// =====================================================================
// dynamic smem layout (float offsets):
//  sWc1h @ 0      (4096)
//  sWinn @ 4096   (320)
//  sBall @ 4416   (1536)   128 tokens x 12
//  region @ 5952  (12416):
//    GEMM1 phase:  sW1 @ 5952 (8192), sX @ 14144 (32 x 132 = 4224)
//    GEMM2 phase:  shT @ 5952 (64 x 132 = 8448)
//    flush phase:  stage @ 5952 (128 x 68 = 8704)
#define P1_SMEM_FLOATS 18368
#define P1_SMEM_BYTES (P1_SMEM_FLOATS * 4)

__global__ __launch_bounds__(256, 2) void phase1_kernel(
    const float* __restrict__ x, const float* __restrict__ W1,
    const float* __restrict__ b1, const float* __restrict__ ln_g,
    const float* __restrict__ ln_b, const float* __restrict__ W_inn,
    const float* __restrict__ b_inn, const float* __restrict__ Wc1,
    const float* __restrict__ bc1) {
    extern __shared__ float sm[];
    float* sWc1h = sm;            // 4096
    float* sWinn = sm + 4096;     // 320
    float* sBall = sm + 4416;     // 1536
    float* region = sm + 5952;
    float* sW1 = region;          // 8192
    float* sX = region + 8192;    // 4224
    float* shT = region;          // 8448 (overlay)
    float* stage = region;        // 8704 (overlay)

    const int tid = threadIdx.x;
    const int t = blockIdx.x >> 2;
    const int b0 = (blockIdx.x & 3) << 7;
    const int colg = tid & 7;
    const int tokg = tid >> 3;

    // x row base for the staging lanes (i = tid + j*256 -> tok, kq)
    const int stok = tid >> 3;        // j contributes +32 tokens per step... recomputed below
    (void)stok;

    // prologue: prefetch x chunk 0 into registers
    float4 xreg[4];
#pragma unroll
    for (int j = 0; j < 4; j++) {
        int i = tid + j * 256;
        int tok = i >> 3, kq = i & 7;
        xreg[j] = __ldg(reinterpret_cast<const float4*>(
                            x + ((size_t)(b0 + tok) * TT + t) * DD) + kq);
    }

    // cooperative weight loads (strided loops — do NOT truncate!)
    for (int i = tid; i < HH * HH; i += 256) sWc1h[i] = Wc1[5 * HH + i];
    for (int i = tid; i < DD * HH; i += 256) sW1[i] = W1[i];
    for (int i = tid; i < HH * 5; i += 256) sWinn[i] = W_inn[i];

    // per-thread constants
    ull b1q[4], bc1q[4];
    const ull* b1p = reinterpret_cast<const ull*>(b1);
    const ull* bc1p = reinterpret_cast<const ull*>(bc1);
#pragma unroll
    for (int q = 0; q < 4; q++) {
        b1q[q] = __ldg(b1p + colg * 4 + q);
        bc1q[q] = __ldg(bc1p + colg * 4 + q);
    }
    float lng[8], lnb[8];
#pragma unroll
    for (int j = 0; j < 8; j++) {
        lng[j] = __ldg(ln_g + colg * 8 + j);
        lnb[j] = __ldg(ln_b + colg * 8 + j);
    }

    // ---- GEMM1: acc[tt][q] over 4 tokens x 8 cols (4 f32x2 pairs) ----
    ull acc[4][4];
#pragma unroll
    for (int tt = 0; tt < 4; tt++)
#pragma unroll
        for (int q = 0; q < 4; q++) acc[tt][q] = b1q[q];

#pragma unroll 1
    for (int c = 0; c < 4; c++) {
        __syncthreads();  // previous chunk's sX reads done (also covers weight loads)
        // stage prefetched chunk c from registers into sX
#pragma unroll
        for (int j = 0; j < 4; j++) {
            int i = tid + j * 256;  // 0..1023
            int tok = i >> 3, kq = i & 7;
            sX[(kq * 4 + 0) * 132 + tok] = xreg[j].x;
            sX[(kq * 4 + 1) * 132 + tok] = xreg[j].y;
            sX[(kq * 4 + 2) * 132 + tok] = xreg[j].z;
            sX[(kq * 4 + 3) * 132 + tok] = xreg[j].w;
        }
        __syncthreads();
        // issue next chunk's global loads early (latency hides under compute)
        if (c < 3) {
#pragma unroll
            for (int j = 0; j < 4; j++) {
                int i = tid + j * 256;
                int tok = i >> 3, kq = i & 7;
                xreg[j] = __ldg(reinterpret_cast<const float4*>(
                                    x + ((size_t)(b0 + tok) * TT + t) * DD +
                                    (c + 1) * 32) +
                                kq);
            }
        }
#pragma unroll 4
        for (int kk = 0; kk < 32; kk++) {
            float4 xv = *reinterpret_cast<const float4*>(&sX[kk * 132 + tokg * 4]);
            const ulonglong2* wr = reinterpret_cast<const ulonglong2*>(
                sW1 + (c * 32 + kk) * HH + colg * 8);
            ulonglong2 l0 = wr[0], l1 = wr[1];
            float xs[4] = {xv.x, xv.y, xv.z, xv.w};
#pragma unroll
            for (int tt = 0; tt < 4; tt++) {
                ull xd = pack2(xs[tt], xs[tt]);
                acc[tt][0] = fma2(xd, l0.x, acc[tt][0]);
                acc[tt][1] = fma2(xd, l0.y, acc[tt][1]);
                acc[tt][2] = fma2(xd, l1.x, acc[tt][2]);
                acc[tt][3] = fma2(xd, l1.y, acc[tt][3]);
            }
        }
    }

    // ---- LN (reduce across 8 col-owner lanes) + gelu ----
    float hv[4][8];
#pragma unroll
    for (int tt = 0; tt < 4; tt++)
#pragma unroll
        for (int q = 0; q < 4; q++) unpack2(acc[tt][q], hv[tt][2 * q], hv[tt][2 * q + 1]);

#pragma unroll
    for (int tt = 0; tt < 4; tt++) {
        float s1 = 0.f, s2 = 0.f;
#pragma unroll
        for (int j = 0; j < 8; j++) { s1 += hv[tt][j]; s2 += hv[tt][j] * hv[tt][j]; }
#pragma unroll
        for (int m = 1; m <= 4; m <<= 1) {
            s1 += __shfl_xor_sync(0xffffffffu, s1, m);
            s2 += __shfl_xor_sync(0xffffffffu, s2, m);
        }
        float mean = s1 * (1.0f / HH);
        float var = s2 * (1.0f / HH) - mean * mean;
        float rstd = rsqrtf(var + 1e-5f);
#pragma unroll
        for (int j = 0; j < 8; j++) {
            float v = (hv[tt][j] - mean) * rstd * lng[j] + lnb[j];
            hv[tt][j] = gelu_fast(v);
        }
    }

    __syncthreads();  // all GEMM1 smem reads done; overwrite region with shT
#pragma unroll
    for (int tt = 0; tt < 4; tt++)
#pragma unroll
        for (int j = 0; j < 8; j++)
            shT[(colg * 8 + j) * 132 + tokg * 4 + tt] = hv[tt][j];
    __syncthreads();

    // ---- GEMM2: po = h @ Wc1_h + bc1 ----
    ull po[4][4];
#pragma unroll
    for (int tt = 0; tt < 4; tt++)
#pragma unroll
        for (int q = 0; q < 4; q++) po[tt][q] = bc1q[q];
#pragma unroll 4
    for (int k = 0; k < HH; k++) {
        float4 hv4 = *reinterpret_cast<const float4*>(&shT[k * 132 + tokg * 4]);
        const ulonglong2* wr =
            reinterpret_cast<const ulonglong2*>(sWc1h + k * HH + colg * 8);
        ulonglong2 l0 = wr[0], l1 = wr[1];
        float hs[4] = {hv4.x, hv4.y, hv4.z, hv4.w};
#pragma unroll
        for (int tt = 0; tt < 4; tt++) {
            ull hd = pack2(hs[tt], hs[tt]);
            po[tt][0] = fma2(hd, l0.x, po[tt][0]);
            po[tt][1] = fma2(hd, l0.y, po[tt][1]);
            po[tt][2] = fma2(hd, l1.x, po[tt][2]);
            po[tt][3] = fma2(hd, l1.y, po[tt][3]);
        }
    }

    // ---- b_all = h @ W_inn + b_inn (one token per thread, tid<128) ----
    if (tid < 128) {
        float bbv[5];
#pragma unroll
        for (int s = 0; s < 5; s++) bbv[s] = __ldg(b_inn + s);
#pragma unroll 4
        for (int k = 0; k < HH; k++) {
            float hk = shT[k * 132 + tid];
#pragma unroll
            for (int s = 0; s < 5; s++) bbv[s] = fmaf(hk, sWinn[k * 5 + s], bbv[s]);
        }
        *reinterpret_cast<float4*>(sBall + tid * 12) =
            make_float4(bbv[0], bbv[1], bbv[2], bbv[3]);
        sBall[tid * 12 + 4] = bbv[4];
        sBall[tid * 12 + 5] = 0.f;
        sBall[tid * 12 + 6] = 0.f;
        sBall[tid * 12 + 7] = 0.f;
    }

    __syncthreads();  // shT reads done; overwrite region with stage
#pragma unroll
    for (int tt = 0; tt < 4; tt++) {
        float f0, f1, f2, f3, f4, f5, f6, f7;
        unpack2(po[tt][0], f0, f1);
        unpack2(po[tt][1], f2, f3);
        unpack2(po[tt][2], f4, f5);
        unpack2(po[tt][3], f6, f7);
        float* d = stage + (tokg * 4 + tt) * 68 + colg * 8;
        *reinterpret_cast<float4*>(d) = make_float4(f0, f1, f2, f3);
        *reinterpret_cast<float4*>(d + 4) = make_float4(f4, f5, f6, f7);
    }
    __syncthreads();

    // ---- coalesced flush ----
    float4* gp = reinterpret_cast<float4*>(g_pre + ((size_t)t * BB + b0) * HH);
#pragma unroll
    for (int j = 0; j < 8; j++) {
        int i = tid + j * 256;  // 0..2047
        int r = i >> 4, cq = i & 15;
        const float* s = stage + r * 68 + cq * 4;
        gp[i] = make_float4(s[0], s[1], s[2], s[3]);
    }
    float4* gb = reinterpret_cast<float4*>(g_ball + ((size_t)t * BB + b0) * 8);
    {
        int i = tid;  // 0..255, exactly 128*8/4 float4s
        int r = i >> 1, cq = i & 1;
        const float* s = sBall + r * 12 + cq * 4;
        gb[i] = make_float4(s[0], s[1], s[2], s[3]);
    }
}

// =====================================================================
// Phase 2 scan (v5): ONE row per warp, 32 lanes, 2 js/lane,
// fixed-point redux.sync.add.s32 reduction. 512 single-warp CTAs.
// Depth-8 register prefetch.
// =====================================================================
#define FXS 1048576.0f            // 2^20
#define FXSI 9.5367431640625e-7f  // 2^-20

__global__ __launch_bounds__(32) void scan_kernel(
    const float* __restrict__ Wc1, const float* __restrict__ Wc2,
    const float* __restrict__ bc2, const float* __restrict__ corr_scale,
    const float* __restrict__ raw_aL, const float* __restrict__ raw_aT,
    const float* __restrict__ raw_g, const float* __restrict__ raw_aR,
    const float* __restrict__ omega, float* __restrict__ out) {
    const int lane = threadIdx.x;
    const int row = blockIdx.x;
    const int j0 = lane * 2;

    float w1s[5][2], w2v[2][5], bc[5];
#pragma unroll
    for (int k = 0; k < 5; k++) {
        w1s[k][0] = __ldg(&Wc1[k * 64 + j0]);
        w1s[k][1] = __ldg(&Wc1[k * 64 + j0 + 1]);
    }
#pragma unroll
    for (int jj = 0; jj < 2; jj++)
#pragma unroll
        for (int k = 0; k < 5; k++) {
            // pre-scale Wc2 by 2^20 so the lane partial is already fixed-point scaled
            w2v[jj][k] = __ldg(&Wc2[(j0 + jj) * 5 + k]) * FXS;
        }
#pragma unroll
    for (int k = 0; k < 5; k++) bc[k] = __ldg(bc2 + k);

    const float aL = sigmoidf_(__ldg(raw_aL)) * 0.15f + 0.85f;
    const float aT = sigmoidf_(__ldg(raw_aT)) * 0.25f + 0.70f;
    const float gg = sigmoidf_(__ldg(raw_g)) * 0.20f + 0.80f;
    const float aR = sigmoidf_(__ldg(raw_aR)) * 0.40f;
    const float om = __ldg(omega);
    const float gc = gg * cosf(om), gs = gg * sinf(om), ngs = -gs;
    const float cs = __ldg(corr_scale);

    float s0 = 0.f, s1 = 0.f, s2v = 0.f, s3 = 0.f, s4 = 0.f;

    float2 pb[8];
    float bbv[8][5];

#pragma unroll
    for (int u = 0; u < 8; u++) {
        pb[u] = __ldg(reinterpret_cast<const float2*>(
            g_pre + ((size_t)u * BB + row) * HH + j0));
        const float* bp = g_ball + ((size_t)u * BB + row) * 8;
        float4 c = __ldg(reinterpret_cast<const float4*>(bp));
        bbv[u][0] = c.x; bbv[u][1] = c.y; bbv[u][2] = c.z; bbv[u][3] = c.w;
        bbv[u][4] = __ldg(bp + 4);
    }

#pragma unroll 1
    for (int tb = 0; tb < TT; tb += 8) {
#pragma unroll
        for (int u = 0; u < 8; u++) {
            const int t = tb + u;
            float sl0 = fmaf(s0, aL, bbv[u][0]);
            float sl1 = fmaf(s1, aT, bbv[u][1]);
            float sl2 = fmaf(s2v, gc, fmaf(s3, gs, bbv[u][2]));
            float sl3 = fmaf(s3, gc, fmaf(s2v, ngs, bbv[u][3]));
            float sl4 = fmaf(s4, aR, bbv[u][4]);

            // z for this lane's 2 columns (shallow trees)
            float za0 = fmaf(sl0, w1s[0][0], pb[u].x);
            float za1 = fmaf(sl0, w1s[0][1], pb[u].y);
            float zb0 = sl1 * w1s[1][0];
            float zb1 = sl1 * w1s[1][1];
            za0 = fmaf(sl2, w1s[2][0], za0);
            za1 = fmaf(sl2, w1s[2][1], za1);
            zb0 = fmaf(sl3, w1s[3][0], zb0);
            zb1 = fmaf(sl3, w1s[3][1], zb1);
            za0 = fmaf(sl4, w1s[4][0], za0);
            za1 = fmaf(sl4, w1s[4][1], za1);
            float z0 = za0 + zb0;
            float z1 = za1 + zb1;

            float hg0 = gelu_fast(z0);
            float hg1 = gelu_fast(z1);

            // lane partials, already scaled by 2^20 (via w2v)
            float p0 = fmaf(hg0, w2v[0][0], hg1 * w2v[1][0]);
            float p1 = fmaf(hg0, w2v[0][1], hg1 * w2v[1][1]);
            float p2 = fmaf(hg0, w2v[0][2], hg1 * w2v[1][2]);
            float p3 = fmaf(hg0, w2v[0][3], hg1 * w2v[1][3]);
            float p4 = fmaf(hg0, w2v[0][4], hg1 * w2v[1][4]);

            // prefetch t+8 (arrays padded, no guard)
            pb[u] = __ldg(reinterpret_cast<const float2*>(
                g_pre + ((size_t)(t + 8) * BB + row) * HH + j0));
            const float* bp = g_ball + ((size_t)(t + 8) * BB + row) * 8;
            float4 c = __ldg(reinterpret_cast<const float4*>(bp));
            bbv[u][0] = c.x; bbv[u][1] = c.y; bbv[u][2] = c.z; bbv[u][3] = c.w;
            bbv[u][4] = __ldg(bp + 4);

            // fixed-point HW warp reduction (broadcasts to all lanes)
            int i0 = redux_add_s32(__float2int_rn(p0));
            int i1 = redux_add_s32(__float2int_rn(p1));
            int i2 = redux_add_s32(__float2int_rn(p2));
            int i3 = redux_add_s32(__float2int_rn(p3));
            int i4 = redux_add_s32(__float2int_rn(p4));

            s0 = fmaf(cs, tanh_fast(fmaf(__int2float_rn(i0), FXSI, bc[0])), sl0);
            s1 = fmaf(cs, tanh_fast(fmaf(__int2float_rn(i1), FXSI, bc[1])), sl1);
            s2v = fmaf(cs, tanh_fast(fmaf(__int2float_rn(i2), FXSI, bc[2])), sl2);
            s3 = fmaf(cs, tanh_fast(fmaf(__int2float_rn(i3), FXSI, bc[3])), sl3);
            s4 = fmaf(cs, tanh_fast(fmaf(__int2float_rn(i4), FXSI, bc[4])), sl4);
        }
    }

    if (lane == 0) {
        out[row * 5 + 0] = s0;
        out[row * 5 + 1] = s1;
        out[row * 5 + 2] = s2v;
        out[row * 5 + 3] = s3;
        out[row * 5 + 4] = s4;
    }
}

// =====================================================================
extern "C" void kernel_launch(void* const* d_in, const int* in_sizes, int n_in,
                              void* d_out, int out_size) {
    const float* x = (const float*)d_in[0];
    const float* W1 = (const float*)d_in[1];
    const float* b1 = (const float*)d_in[2];
    const float* ln_g = (const float*)d_in[3];
    const float* ln_b = (const float*)d_in[4];
    const float* W_inn = (const float*)d_in[5];
    const float* b_inn = (const float*)d_in[6];
    const float* Wc1 = (const float*)d_in[7];
    const float* bc1 = (const float*)d_in[8];
    const float* Wc2 = (const float*)d_in[9];
    const float* bc2 = (const float*)d_in[10];
    const float* corr_scale = (const float*)d_in[11];
    const float* raw_aL = (const float*)d_in[12];
    const float* raw_aT = (const float*)d_in[13];
    const float* raw_g = (const float*)d_in[14];
    const float* raw_aR = (const float*)d_in[15];
    const float* omega = (const float*)d_in[16];
    float* out = (float*)d_out;

    cudaFuncSetAttribute(phase1_kernel, cudaFuncAttributeMaxDynamicSharedMemorySize,
                         P1_SMEM_BYTES);

    // Launch order gives 4 launches/call so ncu (-s 5 -c 1) captures phase1.
    zpad_pre_kernel<<<256, 256>>>();
    phase1_kernel<<<TT * 4, 256, P1_SMEM_BYTES>>>(x, W1, b1, ln_g, ln_b, W_inn,
                                                  b_inn, Wc1, bc1);
    zpad_ball_kernel<<<32, 256>>>();
    scan_kernel<<<BB, 32>>>(Wc1, Wc2, bc2, corr_scale, raw_aL, raw_aT, raw_g,
                            raw_aR, omega, out);
}

// round 8
// speedup vs baseline: 2.3681x; 1.8718x over previous
#include <cuda_runtime.h>
#include <cuda_bf16.h>
#include <math.h>
#include <stdint.h>

#define BB 512
#define TT 512
#define DD 128
#define HH 64

// Scratch, row-major: g_pre[row=b*TT+t][64], g_ball[row][8]. +8 pad rows for
// the scan's depth-8 prefetch (pad values loaded but never consumed).
__device__ float g_pre[((size_t)BB * TT + 8) * HH];
__device__ float g_ball[((size_t)BB * TT + 8) * 8];

// ---------------- helpers ----------------
__device__ __forceinline__ uint32_t s2u(const void* p) {
    uint32_t a;
    asm("{ .reg .u64 t; cvta.to.shared.u64 t, %1; cvt.u32.u64 %0, t; }"
        : "=r"(a) : "l"(p));
    return a;
}
__device__ __forceinline__ void ldsm4(uint32_t addr, uint32_t& r0, uint32_t& r1,
                                      uint32_t& r2, uint32_t& r3) {
    asm volatile("ldmatrix.sync.aligned.m8n8.x4.shared.b16 {%0,%1,%2,%3}, [%4];"
                 : "=r"(r0), "=r"(r1), "=r"(r2), "=r"(r3) : "r"(addr));
}
__device__ __forceinline__ void ldsm4t(uint32_t addr, uint32_t& r0, uint32_t& r1,
                                       uint32_t& r2, uint32_t& r3) {
    asm volatile("ldmatrix.sync.aligned.m8n8.x4.trans.shared.b16 {%0,%1,%2,%3}, [%4];"
                 : "=r"(r0), "=r"(r1), "=r"(r2), "=r"(r3) : "r"(addr));
}
__device__ __forceinline__ void ldsm2t(uint32_t addr, uint32_t& r0, uint32_t& r1) {
    asm volatile("ldmatrix.sync.aligned.m8n8.x2.trans.shared.b16 {%0,%1}, [%2];"
                 : "=r"(r0), "=r"(r1) : "r"(addr));
}
__device__ __forceinline__ void mma16816(float* c, uint32_t a0, uint32_t a1,
                                         uint32_t a2, uint32_t a3, uint32_t b0,
                                         uint32_t b1) {
    asm volatile(
        "mma.sync.aligned.m16n8k16.row.col.f32.bf16.bf16.f32 "
        "{%0,%1,%2,%3},{%4,%5,%6,%7},{%8,%9},{%0,%1,%2,%3};"
        : "+f"(c[0]), "+f"(c[1]), "+f"(c[2]), "+f"(c[3])
        : "r"(a0), "r"(a1), "r"(a2), "r"(a3), "r"(b0), "r"(b1));
}
// split (a,b) -> packed bf16 hi pair (lower16 = a) and residual lo pair
__device__ __forceinline__ void split2(float a, float b, uint32_t& hi, uint32_t& lo) {
    uint32_t h;
    asm("cvt.rn.bf16x2.f32 %0, %1, %2;" : "=r"(h) : "f"(b), "f"(a));
    float ah = __uint_as_float(h << 16);
    float bh = __uint_as_float(h & 0xFFFF0000u);
    float al = a - ah, bl = b - bh;
    uint32_t l;
    asm("cvt.rn.bf16x2.f32 %0, %1, %2;" : "=r"(l) : "f"(bl), "f"(al));
    hi = h;
    lo = l;
}
__device__ __forceinline__ float tanh_fast(float x) {
    float y;
    asm("tanh.approx.f32 %0, %1;" : "=f"(y) : "f"(x));
    return y;
}
__device__ __forceinline__ float gelu_fast(float x) {
    float x2 = x * x;
    float u = x * fmaf(x2, 0.0356774081f, 0.7978845608f);
    float t = tanh_fast(u);
    return x * fmaf(t, 0.5f, 0.5f);
}
__device__ __forceinline__ int redux_add_s32(int v) {
    int r;
    asm("redux.sync.add.s32 %0, %1, 0xffffffff;" : "=r"(r) : "r"(v));
    return r;
}
__device__ __forceinline__ float sigmoidf_(float v) { return 1.0f / (1.0f + expf(-v)); }

// =====================================================================
// Phase 1 (TC): block = 128 consecutive token rows, 256 threads (8 warps).
// GEMM1 (x@W1, K=128) and GEMM2 (h@[Wc1_h|W_inn], 9 n-tiles) via bf16-split
// mma.sync.m16n8k16 (3 products). LN+gelu fused in fragments.
// =====================================================================
// smem layout (bytes):
//  union phase A: aHi@0(10240) aLo@10240(10240) w1Hi@20480(4608) w1Lo@25088(4608)
//  union phase B: hHi@0(18432) hLo@18432(18432)
//  w2Hi@36864(11264) w2Lo@48128(11264)
//  sLng@59392(256) sLnb@59648(256)   total 59904
#define P1_SMEM_BYTES 59904
#define SA 40  // A plane row stride (elements), 80B  -> conflict-free ldmatrix
#define SW 72  // W1/h plane stride, 144B
#define S2 88  // W2 plane stride, 176B

__global__ __launch_bounds__(256, 2) void phase1_kernel(
    const float* __restrict__ x, const float* __restrict__ W1,
    const float* __restrict__ b1, const float* __restrict__ ln_g,
    const float* __restrict__ ln_b, const float* __restrict__ W_inn,
    const float* __restrict__ b_inn, const float* __restrict__ Wc1,
    const float* __restrict__ bc1) {
    extern __shared__ char sm[];
    __nv_bfloat16* aHi = (__nv_bfloat16*)(sm + 0);
    __nv_bfloat16* aLo = (__nv_bfloat16*)(sm + 10240);
    __nv_bfloat16* w1Hi = (__nv_bfloat16*)(sm + 20480);
    __nv_bfloat16* w1Lo = (__nv_bfloat16*)(sm + 25088);
    __nv_bfloat16* hHi = (__nv_bfloat16*)(sm + 0);
    __nv_bfloat16* hLo = (__nv_bfloat16*)(sm + 18432);
    __nv_bfloat16* w2Hi = (__nv_bfloat16*)(sm + 36864);
    __nv_bfloat16* w2Lo = (__nv_bfloat16*)(sm + 48128);
    float* sLng = (float*)(sm + 59392);
    float* sLnb = (float*)(sm + 59648);

    const int tid = threadIdx.x;
    const int lane = tid & 31, warp = tid >> 5;
    const int lm16 = lane & 15, lh16 = lane >> 4;
    const int qr = lane >> 2, qc = (lane & 3) * 2;
    const int row0 = blockIdx.x * 128;

    // prologue: prefetch x chunk0 + W1 chunk0 into registers
    float4 xr[4], wr[2];
#pragma unroll
    for (int j = 0; j < 4; j++) {
        int i = tid + j * 256, r = i >> 3, kq = i & 7;
        xr[j] = __ldg(reinterpret_cast<const float4*>(x + (size_t)(row0 + r) * DD) + kq);
    }
#pragma unroll
    for (int j = 0; j < 2; j++) {
        int i = tid + j * 256, kr = i >> 4, nq = i & 15;
        wr[j] = __ldg(reinterpret_cast<const float4*>(W1 + (size_t)kr * 64) + nq);
    }

    // W2comb = [Wc1_h (64x64) | W_inn (64x5) | 0-pad (64x3)] -> bf16 hi/lo planes
    for (int i = tid; i < 64 * 72; i += 256) {
        int k = i / 72, n = i % 72;
        float f = (n < 64) ? Wc1[(5 + k) * 64 + n]
                           : (n < 69 ? W_inn[k * 5 + (n - 64)] : 0.0f);
        __nv_bfloat16 h = __float2bfloat16(f);
        __nv_bfloat16 l = __float2bfloat16(f - __bfloat162float(h));
        w2Hi[k * S2 + n] = h;
        w2Lo[k * S2 + n] = l;
    }
    if (tid < 64) {
        sLng[tid] = ln_g[tid];
        sLnb[tid] = ln_b[tid];
    }

    // ---- GEMM1 accumulators, init = b1[col] (added pre-LN) ----
    float acc[8][4];
#pragma unroll
    for (int t8 = 0; t8 < 8; t8++) {
        int col = t8 * 8 + qc;
        acc[t8][0] = __ldg(b1 + col);
        acc[t8][1] = __ldg(b1 + col + 1);
        acc[t8][2] = acc[t8][0];
        acc[t8][3] = acc[t8][1];
    }

    const uint32_t uaH = s2u(aHi) + 2 * ((warp * 16 + lm16) * SA + 8 * lh16);
    const uint32_t uaL = s2u(aLo) + 2 * ((warp * 16 + lm16) * SA + 8 * lh16);
    const uint32_t uwH = s2u(w1Hi) + 2 * (lm16 * SW + 8 * lh16);
    const uint32_t uwL = s2u(w1Lo) + 2 * (lm16 * SW + 8 * lh16);

#pragma unroll 1
    for (int c = 0; c < 4; c++) {
        __syncthreads();  // previous chunk's plane reads done
        // stage prefetched regs -> bf16 split planes
#pragma unroll
        for (int j = 0; j < 4; j++) {
            int i = tid + j * 256, r = i >> 3, kq = i & 7;
            uint32_t h0, l0, h1, l1;
            split2(xr[j].x, xr[j].y, h0, l0);
            split2(xr[j].z, xr[j].w, h1, l1);
            int e = r * SA + kq * 4;
            *(uint32_t*)&aHi[e] = h0;
            *(uint32_t*)&aHi[e + 2] = h1;
            *(uint32_t*)&aLo[e] = l0;
            *(uint32_t*)&aLo[e + 2] = l1;
        }
#pragma unroll
        for (int j = 0; j < 2; j++) {
            int i = tid + j * 256, kr = i >> 4, nq = i & 15;
            uint32_t h0, l0, h1, l1;
            split2(wr[j].x, wr[j].y, h0, l0);
            split2(wr[j].z, wr[j].w, h1, l1);
            int e = kr * SW + nq * 4;
            *(uint32_t*)&w1Hi[e] = h0;
            *(uint32_t*)&w1Hi[e + 2] = h1;
            *(uint32_t*)&w1Lo[e] = l0;
            *(uint32_t*)&w1Lo[e + 2] = l1;
        }
        __syncthreads();
        if (c < 3) {  // prefetch next chunk
#pragma unroll
            for (int j = 0; j < 4; j++) {
                int i = tid + j * 256, r = i >> 3, kq = i & 7;
                xr[j] = __ldg(reinterpret_cast<const float4*>(
                                  x + (size_t)(row0 + r) * DD + (c + 1) * 32) + kq);
            }
#pragma unroll
            for (int j = 0; j < 2; j++) {
                int i = tid + j * 256, kr = i >> 4, nq = i & 15;
                wr[j] = __ldg(reinterpret_cast<const float4*>(
                                  W1 + (size_t)((c + 1) * 32 + kr) * 64) + nq);
            }
        }
#pragma unroll
        for (int ks = 0; ks < 2; ks++) {
            uint32_t ah0, ah1, ah2, ah3, al0, al1, al2, al3;
            ldsm4(uaH + ks * 32, ah0, ah1, ah2, ah3);
            ldsm4(uaL + ks * 32, al0, al1, al2, al3);
#pragma unroll
            for (int p = 0; p < 4; p++) {
                uint32_t off = ks * (16 * SW * 2) + p * 32;
                uint32_t bh0, bh1, bh2, bh3, bl0, bl1, bl2, bl3;
                ldsm4t(uwH + off, bh0, bh1, bh2, bh3);
                ldsm4t(uwL + off, bl0, bl1, bl2, bl3);
                mma16816(acc[2 * p], ah0, ah1, ah2, ah3, bh0, bh1);
                mma16816(acc[2 * p], ah0, ah1, ah2, ah3, bl0, bl1);
                mma16816(acc[2 * p], al0, al1, al2, al3, bh0, bh1);
                mma16816(acc[2 * p + 1], ah0, ah1, ah2, ah3, bh2, bh3);
                mma16816(acc[2 * p + 1], ah0, ah1, ah2, ah3, bl2, bl3);
                mma16816(acc[2 * p + 1], al0, al1, al2, al3, bh2, bh3);
            }
        }
    }

    // ---- LN (stats via quad shuffles) + gelu + split into h planes ----
    float sA = 0.f, qA = 0.f, sB = 0.f, qB = 0.f;
#pragma unroll
    for (int t8 = 0; t8 < 8; t8++) {
        sA += acc[t8][0] + acc[t8][1];
        qA += acc[t8][0] * acc[t8][0] + acc[t8][1] * acc[t8][1];
        sB += acc[t8][2] + acc[t8][3];
        qB += acc[t8][2] * acc[t8][2] + acc[t8][3] * acc[t8][3];
    }
#pragma unroll
    for (int m = 1; m <= 2; m <<= 1) {
        sA += __shfl_xor_sync(0xffffffffu, sA, m);
        qA += __shfl_xor_sync(0xffffffffu, qA, m);
        sB += __shfl_xor_sync(0xffffffffu, sB, m);
        qB += __shfl_xor_sync(0xffffffffu, qB, m);
    }
    float mA = sA * (1.0f / 64), vA = qA * (1.0f / 64) - mA * mA;
    float rA_ = rsqrtf(vA + 1e-5f);
    float mB = sB * (1.0f / 64), vB = qB * (1.0f / 64) - mB * mB;
    float rB_ = rsqrtf(vB + 1e-5f);

    __syncthreads();  // all warps done reading A/W1 planes (overlay with h)

    const int rA = warp * 16 + qr, rB = rA + 8;
#pragma unroll
    for (int t8 = 0; t8 < 8; t8++) {
        int col = t8 * 8 + qc;
        float g0 = sLng[col], g1 = sLng[col + 1];
        float bb0 = sLnb[col], bb1 = sLnb[col + 1];
        float vA0 = gelu_fast(fmaf((acc[t8][0] - mA) * rA_, g0, bb0));
        float vA1 = gelu_fast(fmaf((acc[t8][1] - mA) * rA_, g1, bb1));
        float vB0 = gelu_fast(fmaf((acc[t8][2] - mB) * rB_, g0, bb0));
        float vB1 = gelu_fast(fmaf((acc[t8][3] - mB) * rB_, g1, bb1));
        uint32_t h01, l01;
        split2(vA0, vA1, h01, l01);
        *(uint32_t*)&hHi[rA * SW + col] = h01;
        *(uint32_t*)&hLo[rA * SW + col] = l01;
        split2(vB0, vB1, h01, l01);
        *(uint32_t*)&hHi[rB * SW + col] = h01;
        *(uint32_t*)&hLo[rB * SW + col] = l01;
    }
    __syncthreads();

    // ---- GEMM2: [pre | ball] = h @ W2comb + [bc1 | b_inn | 0] ----
    float ac2[9][4];
#pragma unroll
    for (int t8 = 0; t8 < 8; t8++) {
        int col = t8 * 8 + qc;
        ac2[t8][0] = __ldg(bc1 + col);
        ac2[t8][1] = __ldg(bc1 + col + 1);
        ac2[t8][2] = ac2[t8][0];
        ac2[t8][3] = ac2[t8][1];
    }
    ac2[8][0] = (qc < 5) ? __ldg(b_inn + qc) : 0.0f;
    ac2[8][1] = (qc + 1 < 5) ? __ldg(b_inn + qc + 1) : 0.0f;
    ac2[8][2] = ac2[8][0];
    ac2[8][3] = ac2[8][1];

    const uint32_t uhH = s2u(hHi) + 2 * ((warp * 16 + lm16) * SW + 8 * lh16);
    const uint32_t uhL = s2u(hLo) + 2 * ((warp * 16 + lm16) * SW + 8 * lh16);
    const uint32_t u2H = s2u(w2Hi) + 2 * (lm16 * S2 + 8 * lh16);
    const uint32_t u2L = s2u(w2Lo) + 2 * (lm16 * S2 + 8 * lh16);
    const uint32_t u8H = s2u(w2Hi) + 2 * (lm16 * S2 + 64);
    const uint32_t u8L = s2u(w2Lo) + 2 * (lm16 * S2 + 64);

#pragma unroll
    for (int ks = 0; ks < 4; ks++) {
        uint32_t ah0, ah1, ah2, ah3, al0, al1, al2, al3;
        ldsm4(uhH + ks * 32, ah0, ah1, ah2, ah3);
        ldsm4(uhL + ks * 32, al0, al1, al2, al3);
#pragma unroll
        for (int p = 0; p < 4; p++) {
            uint32_t off = ks * (16 * S2 * 2) + p * 32;
            uint32_t bh0, bh1, bh2, bh3, bl0, bl1, bl2, bl3;
            ldsm4t(u2H + off, bh0, bh1, bh2, bh3);
            ldsm4t(u2L + off, bl0, bl1, bl2, bl3);
            mma16816(ac2[2 * p], ah0, ah1, ah2, ah3, bh0, bh1);
            mma16816(ac2[2 * p], ah0, ah1, ah2, ah3, bl0, bl1);
            mma16816(ac2[2 * p], al0, al1, al2, al3, bh0, bh1);
            mma16816(ac2[2 * p + 1], ah0, ah1, ah2, ah3, bh2, bh3);
            mma16816(ac2[2 * p + 1], ah0, ah1, ah2, ah3, bl2, bl3);
            mma16816(ac2[2 * p + 1], al0, al1, al2, al3, bh2, bh3);
        }
        uint32_t b80, b81, c80, c81;
        ldsm2t(u8H + ks * (16 * S2 * 2), b80, b81);
        ldsm2t(u8L + ks * (16 * S2 * 2), c80, c81);
        mma16816(ac2[8], ah0, ah1, ah2, ah3, b80, b81);
        mma16816(ac2[8], ah0, ah1, ah2, ah3, c80, c81);
        mma16816(ac2[8], al0, al1, al2, al3, b80, b81);
    }

    // ---- store pre (rows contiguous 256B) + ball ----
    const int growA = row0 + warp * 16 + qr;
#pragma unroll
    for (int t8 = 0; t8 < 8; t8++) {
        int col = t8 * 8 + qc;
        *(float2*)&g_pre[(size_t)growA * 64 + col] = make_float2(ac2[t8][0], ac2[t8][1]);
        *(float2*)&g_pre[(size_t)(growA + 8) * 64 + col] =
            make_float2(ac2[t8][2], ac2[t8][3]);
    }
    *(float2*)&g_ball[(size_t)growA * 8 + qc] = make_float2(ac2[8][0], ac2[8][1]);
    *(float2*)&g_ball[(size_t)(growA + 8) * 8 + qc] = make_float2(ac2[8][2], ac2[8][3]);
}

// =====================================================================
// Phase 2 scan (v5, row-major scratch): ONE row per warp, 2 js/lane,
// fixed-point redux.sync.add.s32, depth-8 prefetch. 512 CTAs.
// =====================================================================
#define FXS 1048576.0f
#define FXSI 9.5367431640625e-7f

__global__ __launch_bounds__(32) void scan_kernel(
    const float* __restrict__ Wc1, const float* __restrict__ Wc2,
    const float* __restrict__ bc2, const float* __restrict__ corr_scale,
    const float* __restrict__ raw_aL, const float* __restrict__ raw_aT,
    const float* __restrict__ raw_g, const float* __restrict__ raw_aR,
    const float* __restrict__ omega, float* __restrict__ out) {
    const int lane = threadIdx.x;
    const int row = blockIdx.x;  // batch index b
    const int j0 = lane * 2;

    float w1s[5][2], w2v[2][5], bc[5];
#pragma unroll
    for (int k = 0; k < 5; k++) {
        w1s[k][0] = __ldg(&Wc1[k * 64 + j0]);
        w1s[k][1] = __ldg(&Wc1[k * 64 + j0 + 1]);
    }
#pragma unroll
    for (int jj = 0; jj < 2; jj++)
#pragma unroll
        for (int k = 0; k < 5; k++) w2v[jj][k] = __ldg(&Wc2[(j0 + jj) * 5 + k]) * FXS;
#pragma unroll
    for (int k = 0; k < 5; k++) bc[k] = __ldg(bc2 + k);

    const float aL = sigmoidf_(__ldg(raw_aL)) * 0.15f + 0.85f;
    const float aT = sigmoidf_(__ldg(raw_aT)) * 0.25f + 0.70f;
    const float gg = sigmoidf_(__ldg(raw_g)) * 0.20f + 0.80f;
    const float aR = sigmoidf_(__ldg(raw_aR)) * 0.40f;
    const float om = __ldg(omega);
    const float gc = gg * cosf(om), gs = gg * sinf(om), ngs = -gs;
    const float cs = __ldg(corr_scale);

    float s0 = 0.f, s1 = 0.f, s2v = 0.f, s3 = 0.f, s4 = 0.f;

    float2 pb[8];
    float bbv[8][5];
#pragma unroll
    for (int u = 0; u < 8; u++) {
        pb[u] = __ldg(reinterpret_cast<const float2*>(
            g_pre + ((size_t)row * TT + u) * HH + j0));
        const float* bp = g_ball + ((size_t)row * TT + u) * 8;
        float4 c = __ldg(reinterpret_cast<const float4*>(bp));
        bbv[u][0] = c.x; bbv[u][1] = c.y; bbv[u][2] = c.z; bbv[u][3] = c.w;
        bbv[u][4] = __ldg(bp + 4);
    }

#pragma unroll 1
    for (int tb = 0; tb < TT; tb += 8) {
#pragma unroll
        for (int u = 0; u < 8; u++) {
            const int t = tb + u;
            float sl0 = fmaf(s0, aL, bbv[u][0]);
            float sl1 = fmaf(s1, aT, bbv[u][1]);
            float sl2 = fmaf(s2v, gc, fmaf(s3, gs, bbv[u][2]));
            float sl3 = fmaf(s3, gc, fmaf(s2v, ngs, bbv[u][3]));
            float sl4 = fmaf(s4, aR, bbv[u][4]);

            float za0 = fmaf(sl0, w1s[0][0], pb[u].x);
            float za1 = fmaf(sl0, w1s[0][1], pb[u].y);
            float zb0 = sl1 * w1s[1][0];
            float zb1 = sl1 * w1s[1][1];
            za0 = fmaf(sl2, w1s[2][0], za0);
            za1 = fmaf(sl2, w1s[2][1], za1);
            zb0 = fmaf(sl3, w1s[3][0], zb0);
            zb1 = fmaf(sl3, w1s[3][1], zb1);
            za0 = fmaf(sl4, w1s[4][0], za0);
            za1 = fmaf(sl4, w1s[4][1], za1);
            float z0 = za0 + zb0;
            float z1 = za1 + zb1;

            float hg0 = gelu_fast(z0);
            float hg1 = gelu_fast(z1);

            float p0 = fmaf(hg0, w2v[0][0], hg1 * w2v[1][0]);
            float p1 = fmaf(hg0, w2v[0][1], hg1 * w2v[1][1]);
            float p2 = fmaf(hg0, w2v[0][2], hg1 * w2v[1][2]);
            float p3 = fmaf(hg0, w2v[0][3], hg1 * w2v[1][3]);
            float p4 = fmaf(hg0, w2v[0][4], hg1 * w2v[1][4]);

            // prefetch t+8 (rows padded; values past t=511 never consumed)
            pb[u] = __ldg(reinterpret_cast<const float2*>(
                g_pre + ((size_t)row * TT + t + 8) * HH + j0));
            const float* bp = g_ball + ((size_t)row * TT + t + 8) * 8;
            float4 c = __ldg(reinterpret_cast<const float4*>(bp));
            bbv[u][0] = c.x; bbv[u][1] = c.y; bbv[u][2] = c.z; bbv[u][3] = c.w;
            bbv[u][4] = __ldg(bp + 4);

            int i0 = redux_add_s32(__float2int_rn(p0));
            int i1 = redux_add_s32(__float2int_rn(p1));
            int i2 = redux_add_s32(__float2int_rn(p2));
            int i3 = redux_add_s32(__float2int_rn(p3));
            int i4 = redux_add_s32(__float2int_rn(p4));

            s0 = fmaf(cs, tanh_fast(fmaf(__int2float_rn(i0), FXSI, bc[0])), sl0);
            s1 = fmaf(cs, tanh_fast(fmaf(__int2float_rn(i1), FXSI, bc[1])), sl1);
            s2v = fmaf(cs, tanh_fast(fmaf(__int2float_rn(i2), FXSI, bc[2])), sl2);
            s3 = fmaf(cs, tanh_fast(fmaf(__int2float_rn(i3), FXSI, bc[3])), sl3);
            s4 = fmaf(cs, tanh_fast(fmaf(__int2float_rn(i4), FXSI, bc[4])), sl4);
        }
    }

    if (lane == 0) {
        out[row * 5 + 0] = s0;
        out[row * 5 + 1] = s1;
        out[row * 5 + 2] = s2v;
        out[row * 5 + 3] = s3;
        out[row * 5 + 4] = s4;
    }
}

// =====================================================================
extern "C" void kernel_launch(void* const* d_in, const int* in_sizes, int n_in,
                              void* d_out, int out_size) {
    const float* x = (const float*)d_in[0];
    const float* W1 = (const float*)d_in[1];
    const float* b1 = (const float*)d_in[2];
    const float* ln_g = (const float*)d_in[3];
    const float* ln_b = (const float*)d_in[4];
    const float* W_inn = (const float*)d_in[5];
    const float* b_inn = (const float*)d_in[6];
    const float* Wc1 = (const float*)d_in[7];
    const float* bc1 = (const float*)d_in[8];
    const float* Wc2 = (const float*)d_in[9];
    const float* bc2 = (const float*)d_in[10];
    const float* corr_scale = (const float*)d_in[11];
    const float* raw_aL = (const float*)d_in[12];
    const float* raw_aT = (const float*)d_in[13];
    const float* raw_g = (const float*)d_in[14];
    const float* raw_aR = (const float*)d_in[15];
    const float* omega = (const float*)d_in[16];
    float* out = (float*)d_out;

    cudaFuncSetAttribute(phase1_kernel, cudaFuncAttributeMaxDynamicSharedMemorySize,
                         P1_SMEM_BYTES);

    phase1_kernel<<<(BB * TT) / 128, 256, P1_SMEM_BYTES>>>(
        x, W1, b1, ln_g, ln_b, W_inn, b_inn, Wc1, bc1);
    scan_kernel<<<BB, 32>>>(Wc1, Wc2, bc2, corr_scale, raw_aL, raw_aT, raw_g,
                            raw_aR, omega, out);
}